// round 14
// baseline (speedup 1.0000x reference)
#include <cuda_runtime.h>

#define NB 2
#define N1 4096
#define N2 16384
#define CF 64
#define KNN 8

#define GS    64                    // x-slabs per batch
#define GY    64                    // y-buckets per slab
#define NCELL (GS * GY)             // 4096 cells per batch
#define XMIN  -4.2f
#define BWX   0.13125f              // 8.4 / 64
#define BINVX 7.61904762f

// Scratch (static __device__ arrays per allocation rules)
__device__ int    g_cst[NB * (NCELL + 1)];  // cell start offsets + sentinel
__device__ float4 g_spts[NB * N1];          // cell-sorted pts, w = orig idx bits
__device__ float  g_gtab[NB * N1 * CF];     // W1_feat@feat + W1_xyz@xyz1 + b1
__device__ int    g_idx[NB * N2 * KNN];     // knn indices (original index space)

__device__ __forceinline__ int bidx(float v) {
    return min(max(__float2int_rd((v - XMIN) * BINVX), 0), GS - 1);
}

// ---------------------------------------------------------------------------
// Kernel 1: fused cell build. One 1024-thread block per batch.
// smem histogram -> block scan -> scatter with smem-atomic cursors.
// ---------------------------------------------------------------------------
__global__ void __launch_bounds__(1024) build_kernel(const float* __restrict__ xyz1) {
    __shared__ int sCnt[NCELL];     // 16 KB: histogram, then cursor
    __shared__ int sTot[1024];      // 4 KB: scan tree

    int b = blockIdx.x, t = threadIdx.x;
    const float* p = xyz1 + (size_t)b * 3 * N1;

#pragma unroll
    for (int k = 0; k < NCELL / 1024; k++) sCnt[t + k * 1024] = 0;
    __syncthreads();

    float px[4], py[4], pz[4]; int cell[4];
#pragma unroll
    for (int k = 0; k < 4; k++) {
        int j = t + k * 1024;
        px[k] = p[j]; py[k] = p[N1 + j]; pz[k] = p[2 * N1 + j];
        cell[k] = bidx(px[k]) * GY + bidx(py[k]);
        atomicAdd(&sCnt[cell[k]], 1);
    }
    __syncthreads();

    int base = t * 4;
    int v[4], s[4];
    int run = 0;
#pragma unroll
    for (int i = 0; i < 4; i++) { v[i] = sCnt[base + i]; run += v[i]; s[i] = run; }
    sTot[t] = run;
    __syncthreads();
#pragma unroll
    for (int off = 1; off < 1024; off <<= 1) {
        int u = (t >= off) ? sTot[t - off] : 0;
        __syncthreads();
        sTot[t] += u;
        __syncthreads();
    }
    int ex = sTot[t] - run;
    int* cst = g_cst + b * (NCELL + 1);
#pragma unroll
    for (int i = 0; i < 4; i++) {
        int start = ex + s[i] - v[i];
        cst[base + i] = start;
        sCnt[base + i] = start;     // becomes scatter cursor
    }
    if (t == 1023) cst[NCELL] = N1; // sentinel
    __syncthreads();

    float4* sp = g_spts + (size_t)b * N1;
#pragma unroll
    for (int k = 0; k < 4; k++) {
        int j = t + k * 1024;
        int pos = atomicAdd(&sCnt[cell[k]], 1);
        sp[pos] = make_float4(px[k], py[k], pz[k], __int_as_float(j));
    }
}

// ---------------------------------------------------------------------------
// Kernel 2: per-target transform  g[b][j][o] = sum_c W1[o][c]*in[c] + b1[o]
// ---------------------------------------------------------------------------
__global__ void __launch_bounds__(256) gmat_kernel(const float* __restrict__ feat1,
                                                   const float* __restrict__ xyz1,
                                                   const float* __restrict__ W1,
                                                   const float* __restrict__ b1) {
    __shared__ __align__(16) float sIn[67 * 64];
    __shared__ float sW[64 * 67];
    __shared__ float sB[64];

    int b  = blockIdx.x >> 6;
    int j0 = (blockIdx.x & 63) * 64;
    int t  = threadIdx.x;

    for (int i = t; i < 64 * 67; i += 256) sW[i] = W1[i];
    if (t < 64) sB[t] = b1[t];

    const float* fb = feat1 + (size_t)b * CF * N1;
    for (int i = t; i < 64 * 64; i += 256) {
        int c = i >> 6, j = i & 63;
        sIn[c * 64 + j] = fb[c * N1 + j0 + j];
    }
    const float* xb = xyz1 + (size_t)b * 3 * N1;
    if (t < 3 * 64) {
        int c = t >> 6, j = t & 63;
        sIn[(64 + c) * 64 + j] = xb[c * N1 + j0 + j];
    }
    __syncthreads();

    int o = t & 63, jg = t >> 6;
    float acc[16];
    float bb = sB[o];
#pragma unroll
    for (int ii = 0; ii < 16; ii++) acc[ii] = bb;

    for (int c = 0; c < 67; c++) {
        float w = sW[o * 67 + c];
        const float4* in4 = (const float4*)(sIn + c * 64 + jg * 16);
#pragma unroll
        for (int q4 = 0; q4 < 4; q4++) {
            float4 v = in4[q4];
            acc[q4 * 4 + 0] = fmaf(w, v.x, acc[q4 * 4 + 0]);
            acc[q4 * 4 + 1] = fmaf(w, v.y, acc[q4 * 4 + 1]);
            acc[q4 * 4 + 2] = fmaf(w, v.z, acc[q4 * 4 + 2]);
            acc[q4 * 4 + 3] = fmaf(w, v.w, acc[q4 * 4 + 3]);
        }
    }

    float* gp = g_gtab + ((size_t)b * N1 + j0 + jg * 16) * CF + o;
#pragma unroll
    for (int ii = 0; ii < 16; ii++) gp[ii * CF] = acc[ii];
}

// ---------------------------------------------------------------------------
// Kernel 3: top-8 KNN, one warp per query, 2-D (x-slab, y-bucket) pruning.
// Slab-major storage: each slab's y-range is contiguous -> 32-lane chunks.
// Per-slab y-bound exact (bucket-edge distances; clamped edge buckets safe).
// Warm start: full-warp bitonic sort around the query's own cell.
// ---------------------------------------------------------------------------
__device__ __forceinline__ void scan_chunk(const float4* __restrict__ SP,
                                           int base, int c, int wst, int wen,
                                           float qx, float qy, float qz,
                                           float& dk_own, int& ik_own,
                                           float& dk7, int lane) {
    const unsigned FULL = 0xffffffffu;
    float d = 3.4e38f; int iw = 0;
    int pos = base + lane;
    if (lane < c && (pos < wst || pos >= wen)) {    // skip warm-start window
        float4 p = SP[pos];
        float dx = p.x - qx, dy = p.y - qy, dz = p.z - qz;
        d = fmaf(dz, dz, fmaf(dy, dy, dx * dx));
        iw = __float_as_int(p.w);
    }
    unsigned m = __ballot_sync(FULL, d < dk7);
    while (m) {                            // warp-uniform candidate loop
        int src = __ffs(m) - 1;
        m &= m - 1;
        float dc = __shfl_sync(FULL, d, src);
        if (dc < dk7) {                    // recheck vs tightened threshold
            int jc = __shfl_sync(FULL, iw, src);
            unsigned gt = __ballot_sync(FULL, (lane < 8) && (dk_own > dc));
            int pp = __ffs(gt) - 1;
            float upd = __shfl_up_sync(FULL, dk_own, 1);
            int   upj = __shfl_up_sync(FULL, ik_own, 1);
            if (lane < 8) {
                if (lane == pp)     { dk_own = dc;  ik_own = jc;  }
                else if (lane > pp) { dk_own = upd; ik_own = upj; }
            }
            dk7 = __shfl_sync(FULL, dk_own, 7);
        }
    }
}

__device__ __forceinline__ void process_slab(const float4* __restrict__ SP,
                                             const int* __restrict__ CST,
                                             int s, float gap, int wst, int wen,
                                             float qx, float qy, float qz,
                                             float& dk_own, int& ik_own,
                                             float& dk7, int lane) {
    float bb = dk7 - gap * gap;            // >= 0 at call sites
    float bound = sqrtf(bb) + 1e-5f;       // inflated vs rounding
    int ylo = bidx(qy - bound);
    int yhi = bidx(qy + bound);
    int r0 = CST[s * GY + ylo];
    int r1 = CST[s * GY + yhi + 1];
    for (int p = r0; p < r1; p += 32)
        scan_chunk(SP, p, min(r1 - p, 32), wst, wen,
                   qx, qy, qz, dk_own, ik_own, dk7, lane);
}

__global__ void __launch_bounds__(512) knn_kernel(const float* __restrict__ xyz2) {
    const unsigned FULL = 0xffffffffu;
    int t    = threadIdx.x;
    int lane = t & 31;
    int w    = t >> 5;               // 0..15 : query within block
    int b    = blockIdx.x >> 10;     // 1024 blocks per batch
    int q    = ((blockIdx.x & 1023) << 4) + w;

    const float* xq = xyz2 + (size_t)b * 3 * N2;
    float qx = xq[q], qy = xq[N2 + q], qz = xq[2 * N2 + q];

    const float4* SP  = g_spts + b * N1;
    const int*    CST = g_cst  + b * (NCELL + 1);

    int s  = bidx(qx);
    int yb = bidx(qy);
    int ss = CST[s * GY];            // slab start
    int se = CST[(s + 1) * GY];      // slab end (sentinel-safe for s=63)
    int cs = CST[s * GY + yb];       // query's cell start

    // --- warm start: bitonic sort of <=32 positions around the query cell ---
    int cnt = min(se - ss, 32);
    int wst = min(max(cs - 16, ss), se - cnt);
    int wen = wst + cnt;
    float d = 3.4e38f; int id = 0;
    if (lane < cnt) {
        float4 p = SP[wst + lane];
        float dx = p.x - qx, dy = p.y - qy, dz = p.z - qz;
        d = fmaf(dz, dz, fmaf(dy, dy, dx * dx));
        id = __float_as_int(p.w);
    }
#pragma unroll
    for (int k = 2; k <= 32; k <<= 1) {
#pragma unroll
        for (int j = k >> 1; j > 0; j >>= 1) {
            float od = __shfl_xor_sync(FULL, d, j);
            int   oi = __shfl_xor_sync(FULL, id, j);
            bool takeMin = ((lane & j) == 0) == ((lane & k) == 0);
            if ((od < d) == takeMin) { d = od; id = oi; }
        }
    }
    float dk_own = d;                // lane r (r<8) holds list element r, ascending
    int   ik_own = id;               // original target index
    float dk7    = __shfl_sync(FULL, d, 7);

    // center slab remainder (warm window excluded inside scan_chunk)
    process_slab(SP, CST, s, 0.f, wst, wen, qx, qy, qz, dk_own, ik_own, dk7, lane);

    // --- two-pointer slab expansion with exact x-edge bounds ---
    int sl = s, sr = s;
#pragma unroll 1
    while (sl > 0 || sr < GS - 1) {
        float gl = (sl > 0)      ? qx - (XMIN + sl * BWX)       : 3.4e38f;
        float gr = (sr < GS - 1) ? (XMIN + (sr + 1) * BWX) - qx : 3.4e38f;
        bool left = gl <= gr;
        float gap = fmaxf(left ? gl : gr, 0.f);
        if (gap * gap > dk7) break;
        int ns = left ? --sl : ++sr;
        process_slab(SP, CST, ns, gap, -1, -1, qx, qy, qz, dk_own, ik_own, dk7, lane);
    }

    if (lane < 8)
        g_idx[((size_t)b * N2 + q) * KNN + lane] = ik_own;
}

// ---------------------------------------------------------------------------
// Kernel 4: upsample, ONE WARP PER QUERY.
// lane = g*8+n: handles neighbor n (of 8), channel group [16g, 16g+16).
// 3 scalar accumulators per lane; channel-reduce via shfl_xor(8,16);
// 3 softmaxes over n via shfl_xor(1,2,4); flow dot; lane 0 writes.
// h_n = lrelu(g[idx_n] - W1_xyz @ q);  logits = W2 . h  (b2 cancels).
// ---------------------------------------------------------------------------
__global__ void __launch_bounds__(512) up_kernel(const float* __restrict__ xyz2,
                                                 const float* __restrict__ flow,
                                                 const float* __restrict__ W1,
                                                 const float* __restrict__ W2,
                                                 float* __restrict__ out) {
    __shared__ float sWx[64 * 3];   // [o][c]  (xyz columns of W1)
    __shared__ float sW2[3 * 64];   // [j][o]

    const unsigned FULL = 0xffffffffu;
    int t    = threadIdx.x;
    int lane = t & 31;
    int w    = t >> 5;               // 0..15 : query within block
    int b    = blockIdx.x >> 10;     // 1024 blocks per batch
    int q    = ((blockIdx.x & 1023) << 4) + w;

    if (t < 192) { int o = t / 3, c = t - o * 3; sWx[t] = W1[o * 67 + 64 + c]; }
    if (t < 192) sW2[t] = W2[t];
    __syncthreads();

    const float* xq = xyz2 + (size_t)b * 3 * N2;
    float qx = xq[q], qy = xq[N2 + q], qz = xq[2 * N2 + q];

    int n = lane & 7;                // neighbor owned by this lane
    int g = lane >> 3;               // channel group [16g, 16g+16)

    int myidx = 0;
    if (lane < 8) myidx = g_idx[((size_t)b * N2 + q) * KNN + lane];
    int jn = __shfl_sync(FULL, myidx, n);

    const float* gr = g_gtab + ((size_t)b * N1 + jn) * CF;
    float a0 = 0.f, a1 = 0.f, a2 = 0.f;
#pragma unroll
    for (int oo = 0; oo < 4; oo++) {
        int o4 = g * 4 + oo;
        float4 g4 = ((const float4*)gr)[o4];
        int ob = o4 * 4;
        float h;
#pragma unroll
        for (int i = 0; i < 4; i++) {
            float gc = (i == 0) ? g4.x : (i == 1) ? g4.y : (i == 2) ? g4.z : g4.w;
            int o = ob + i;
            float uu = fmaf(sWx[o * 3 + 2], qz,
                            fmaf(sWx[o * 3 + 1], qy, sWx[o * 3] * qx));
            h = gc - uu;
            h = h >= 0.f ? h : 0.1f * h;
            a0 = fmaf(sW2[o], h, a0);
            a1 = fmaf(sW2[64 + o], h, a1);
            a2 = fmaf(sW2[128 + o], h, a2);
        }
    }
    // reduce over channel groups (xor 8, 16): every lane gets the full logit
    a0 += __shfl_xor_sync(FULL, a0, 8);  a0 += __shfl_xor_sync(FULL, a0, 16);
    a1 += __shfl_xor_sync(FULL, a1, 8);  a1 += __shfl_xor_sync(FULL, a1, 16);
    a2 += __shfl_xor_sync(FULL, a2, 8);  a2 += __shfl_xor_sync(FULL, a2, 16);

    // 3 softmaxes over the 8 neighbors (within each 8-lane group)
    float m0 = a0, m1 = a1, m2 = a2;
#pragma unroll
    for (int dd = 1; dd <= 4; dd <<= 1) {
        m0 = fmaxf(m0, __shfl_xor_sync(FULL, m0, dd));
        m1 = fmaxf(m1, __shfl_xor_sync(FULL, m1, dd));
        m2 = fmaxf(m2, __shfl_xor_sync(FULL, m2, dd));
    }
    float e0 = __expf(a0 - m0), e1 = __expf(a1 - m1), e2 = __expf(a2 - m2);
    float s0 = e0, s1 = e1, s2 = e2;
#pragma unroll
    for (int dd = 1; dd <= 4; dd <<= 1) {
        s0 += __shfl_xor_sync(FULL, s0, dd);
        s1 += __shfl_xor_sync(FULL, s1, dd);
        s2 += __shfl_xor_sync(FULL, s2, dd);
    }

    // weighted flow sum (group g=0 only does real loads; reduction stays
    // within each 8-lane group so other groups' values are irrelevant)
    float f0 = 0.f, f1 = 0.f, f2 = 0.f;
    if (g == 0) {
        const float* fb = flow + (size_t)b * 3 * N1;
        f0 = fb[jn]; f1 = fb[N1 + jn]; f2 = fb[2 * N1 + jn];
    }
    float r0 = e0 * f0, r1 = e1 * f1, r2 = e2 * f2;
#pragma unroll
    for (int dd = 1; dd <= 4; dd <<= 1) {
        r0 += __shfl_xor_sync(FULL, r0, dd);
        r1 += __shfl_xor_sync(FULL, r1, dd);
        r2 += __shfl_xor_sync(FULL, r2, dd);
    }

    if (lane == 0) {
        float* ob_ = out + (size_t)b * 3 * N2;
        ob_[q]          = r0 / s0;
        ob_[N2 + q]     = r1 / s1;
        ob_[2 * N2 + q] = r2 / s2;
    }
}

// ---------------------------------------------------------------------------
extern "C" void kernel_launch(void* const* d_in, const int* in_sizes, int n_in,
                              void* d_out, int out_size) {
    const float* xyz1  = (const float*)d_in[0];
    const float* xyz2  = (const float*)d_in[1];
    const float* feat1 = (const float*)d_in[2];
    const float* flow  = (const float*)d_in[3];
    const float* W1    = (const float*)d_in[4];
    const float* b1    = (const float*)d_in[5];
    const float* W2    = (const float*)d_in[6];
    // b2 (d_in[7]) unused: constant shift cancels in softmax over k.
    float* out = (float*)d_out;

    build_kernel<<<NB, 1024>>>(xyz1);
    gmat_kernel<<<NB * 64, 256>>>(feat1, xyz1, W1, b1);
    knn_kernel<<<NB * 1024, 512>>>(xyz2);
    up_kernel<<<NB * 1024, 512>>>(xyz2, flow, W1, W2, out);
}

// round 15
// speedup vs baseline: 1.9160x; 1.9160x over previous
#include <cuda_runtime.h>

#define NB 2
#define N1 4096
#define N2 16384
#define CF 64
#define KNN 8

#define GS    64                    // x-slabs per batch
#define GY    128                   // y-buckets per slab
#define NCELL (GS * GY)             // 8192 cells per batch
#define XMIN  -4.2f
#define BWX   0.13125f              // 8.4 / 64
#define BINVX 7.61904762f
#define BINVY 15.23809524f          // 128 / 8.4

// Scratch (static __device__ arrays per allocation rules)
__device__ int    g_cst[NB * (NCELL + 1)];  // cell start offsets + sentinel
__device__ float4 g_spts[NB * N1];          // cell-sorted pts, w = orig idx bits
__device__ float  g_gtab[NB * N1 * CF];     // W1_feat@feat + W1_xyz@xyz1 + b1
__device__ int    g_idx[NB * N2 * KNN];     // knn indices (original index space)

__device__ __forceinline__ int bidx(float v) {
    return min(max(__float2int_rd((v - XMIN) * BINVX), 0), GS - 1);
}
__device__ __forceinline__ int bidy(float v) {
    return min(max(__float2int_rd((v - XMIN) * BINVY), 0), GY - 1);
}

// ---------------------------------------------------------------------------
// Kernel 1: FUSED prep. Blocks [0, NB): cell build (histogram/scan/scatter).
// Blocks [NB, NB + NB*64): per-target transform g = W1@[feat;xyz] + b1.
// The two jobs are independent and run concurrently in one launch.
// ---------------------------------------------------------------------------
__global__ void __launch_bounds__(1024) prep_kernel(const float* __restrict__ feat1,
                                                    const float* __restrict__ xyz1,
                                                    const float* __restrict__ W1,
                                                    const float* __restrict__ b1) {
    __shared__ __align__(16) float sraw[9216];   // 36 KB overlay
    int t = threadIdx.x;

    if (blockIdx.x < NB) {
        // ============================ build ================================
        int* sCnt = (int*)sraw;                  // NCELL ints (32 KB)
        int* sTot = (int*)(sraw + NCELL);        // 1024 ints  (4 KB)
        int b = blockIdx.x;
        const float* p = xyz1 + (size_t)b * 3 * N1;

#pragma unroll
        for (int k = 0; k < NCELL / 1024; k++) sCnt[t + k * 1024] = 0;
        __syncthreads();

        float px[4], py[4], pz[4]; int cell[4];
#pragma unroll
        for (int k = 0; k < 4; k++) {
            int j = t + k * 1024;
            px[k] = p[j]; py[k] = p[N1 + j]; pz[k] = p[2 * N1 + j];
            cell[k] = bidx(px[k]) * GY + bidy(py[k]);
            atomicAdd(&sCnt[cell[k]], 1);
        }
        __syncthreads();

        int base = t * 8;
        int v[8], s[8];
        int run = 0;
#pragma unroll
        for (int i = 0; i < 8; i++) { v[i] = sCnt[base + i]; run += v[i]; s[i] = run; }
        sTot[t] = run;
        __syncthreads();
#pragma unroll
        for (int off = 1; off < 1024; off <<= 1) {
            int u = (t >= off) ? sTot[t - off] : 0;
            __syncthreads();
            sTot[t] += u;
            __syncthreads();
        }
        int ex = sTot[t] - run;
        int* cst = g_cst + b * (NCELL + 1);
#pragma unroll
        for (int i = 0; i < 8; i++) {
            int start = ex + s[i] - v[i];
            cst[base + i] = start;
            sCnt[base + i] = start;     // becomes scatter cursor
        }
        if (t == 1023) cst[NCELL] = N1; // sentinel
        __syncthreads();

        float4* sp = g_spts + (size_t)b * N1;
#pragma unroll
        for (int k = 0; k < 4; k++) {
            int j = t + k * 1024;
            int pos = atomicAdd(&sCnt[cell[k]], 1);
            sp[pos] = make_float4(px[k], py[k], pz[k], __int_as_float(j));
        }
    } else {
        // ============================ gmat =================================
        float* sIn = sraw;                       // 67*64 floats
        float* sW  = sraw + 67 * 64;             // 64*67 floats
        float* sB  = sraw + 2 * 67 * 64;         // 64 floats (total 8640)
        int bb = blockIdx.x - NB;
        int b  = bb >> 6;
        int j0 = (bb & 63) * 64;

        for (int i = t; i < 64 * 67; i += 1024) sW[i] = W1[i];
        if (t < 64) sB[t] = b1[t];

        const float* fb = feat1 + (size_t)b * CF * N1;
        for (int i = t; i < 64 * 64; i += 1024) {
            int c = i >> 6, j = i & 63;
            sIn[c * 64 + j] = fb[c * N1 + j0 + j];
        }
        const float* xb = xyz1 + (size_t)b * 3 * N1;
        if (t < 3 * 64) {
            int c = t >> 6, j = t & 63;
            sIn[(64 + c) * 64 + j] = xb[c * N1 + j0 + j];
        }
        __syncthreads();

        int o = t & 63, jg = t >> 6;     // jg in 0..15, 4 consecutive j each
        float acc[4];
        float bv = sB[o];
#pragma unroll
        for (int i = 0; i < 4; i++) acc[i] = bv;

        for (int c = 0; c < 67; c++) {
            float w = sW[o * 67 + c];
            float4 v4 = ((const float4*)(sIn + c * 64))[jg];
            acc[0] = fmaf(w, v4.x, acc[0]);
            acc[1] = fmaf(w, v4.y, acc[1]);
            acc[2] = fmaf(w, v4.z, acc[2]);
            acc[3] = fmaf(w, v4.w, acc[3]);
        }

        float* gp = g_gtab + ((size_t)b * N1 + j0 + jg * 4) * CF + o;
#pragma unroll
        for (int i = 0; i < 4; i++) gp[i * CF] = acc[i];
    }
}

// ---------------------------------------------------------------------------
// Kernel 2: top-8 KNN, one warp per query, 2-D (x-slab, y-bucket) pruning.
// Slab-major storage: each slab's y-range is contiguous -> 32-lane chunks.
// Per-slab y-bound exact (bucket-edge distances; clamped edge buckets safe).
// Warm start: full-warp bitonic sort around the query's own cell.
// ---------------------------------------------------------------------------
__device__ __forceinline__ void scan_chunk(const float4* __restrict__ SP,
                                           int base, int c, int wst, int wen,
                                           float qx, float qy, float qz,
                                           float& dk_own, int& ik_own,
                                           float& dk7, int lane) {
    const unsigned FULL = 0xffffffffu;
    float d = 3.4e38f; int iw = 0;
    int pos = base + lane;
    if (lane < c && (pos < wst || pos >= wen)) {    // skip warm-start window
        float4 p = SP[pos];
        float dx = p.x - qx, dy = p.y - qy, dz = p.z - qz;
        d = fmaf(dz, dz, fmaf(dy, dy, dx * dx));
        iw = __float_as_int(p.w);
    }
    unsigned m = __ballot_sync(FULL, d < dk7);
    while (m) {                            // warp-uniform candidate loop
        int src = __ffs(m) - 1;
        m &= m - 1;
        float dc = __shfl_sync(FULL, d, src);
        if (dc < dk7) {                    // recheck vs tightened threshold
            int jc = __shfl_sync(FULL, iw, src);
            unsigned gt = __ballot_sync(FULL, (lane < 8) && (dk_own > dc));
            int pp = __ffs(gt) - 1;
            float upd = __shfl_up_sync(FULL, dk_own, 1);
            int   upj = __shfl_up_sync(FULL, ik_own, 1);
            if (lane < 8) {
                if (lane == pp)     { dk_own = dc;  ik_own = jc;  }
                else if (lane > pp) { dk_own = upd; ik_own = upj; }
            }
            dk7 = __shfl_sync(FULL, dk_own, 7);
        }
    }
}

__device__ __forceinline__ void process_slab(const float4* __restrict__ SP,
                                             const int* __restrict__ CST,
                                             int s, float gap, int wst, int wen,
                                             float qx, float qy, float qz,
                                             float& dk_own, int& ik_own,
                                             float& dk7, int lane) {
    float bb = dk7 - gap * gap;            // >= 0 at call sites
    float bound = sqrtf(bb) + 1e-5f;       // inflated vs rounding
    int ylo = bidy(qy - bound);
    int yhi = bidy(qy + bound);
    int r0 = CST[s * GY + ylo];
    int r1 = CST[s * GY + yhi + 1];
    for (int p = r0; p < r1; p += 32)
        scan_chunk(SP, p, min(r1 - p, 32), wst, wen,
                   qx, qy, qz, dk_own, ik_own, dk7, lane);
}

__global__ void __launch_bounds__(512) knn_kernel(const float* __restrict__ xyz2) {
    const unsigned FULL = 0xffffffffu;
    int t    = threadIdx.x;
    int lane = t & 31;
    int w    = t >> 5;               // 0..15 : query within block
    int b    = blockIdx.x >> 10;     // 1024 blocks per batch
    int q    = ((blockIdx.x & 1023) << 4) + w;

    const float* xq = xyz2 + (size_t)b * 3 * N2;
    float qx = xq[q], qy = xq[N2 + q], qz = xq[2 * N2 + q];

    const float4* SP  = g_spts + b * N1;
    const int*    CST = g_cst  + b * (NCELL + 1);

    int s  = bidx(qx);
    int yb = bidy(qy);
    int ss = CST[s * GY];            // slab start
    int se = CST[(s + 1) * GY];      // slab end (sentinel-safe for s=63)
    int cs = CST[s * GY + yb];       // query's cell start

    // --- warm start: bitonic sort of <=32 positions around the query cell ---
    int cnt = min(se - ss, 32);
    int wst = min(max(cs - 16, ss), se - cnt);
    int wen = wst + cnt;
    float d = 3.4e38f; int id = 0;
    if (lane < cnt) {
        float4 p = SP[wst + lane];
        float dx = p.x - qx, dy = p.y - qy, dz = p.z - qz;
        d = fmaf(dz, dz, fmaf(dy, dy, dx * dx));
        id = __float_as_int(p.w);
    }
#pragma unroll
    for (int k = 2; k <= 32; k <<= 1) {
#pragma unroll
        for (int j = k >> 1; j > 0; j >>= 1) {
            float od = __shfl_xor_sync(FULL, d, j);
            int   oi = __shfl_xor_sync(FULL, id, j);
            bool takeMin = ((lane & j) == 0) == ((lane & k) == 0);
            if ((od < d) == takeMin) { d = od; id = oi; }
        }
    }
    float dk_own = d;                // lane r (r<8) holds list element r, ascending
    int   ik_own = id;               // original target index
    float dk7    = __shfl_sync(FULL, d, 7);

    // center slab remainder (warm window excluded inside scan_chunk)
    process_slab(SP, CST, s, 0.f, wst, wen, qx, qy, qz, dk_own, ik_own, dk7, lane);

    // --- two-pointer slab expansion with exact x-edge bounds ---
    int sl = s, sr = s;
#pragma unroll 1
    while (sl > 0 || sr < GS - 1) {
        float gl = (sl > 0)      ? qx - (XMIN + sl * BWX)       : 3.4e38f;
        float gr = (sr < GS - 1) ? (XMIN + (sr + 1) * BWX) - qx : 3.4e38f;
        bool left = gl <= gr;
        float gap = fmaxf(left ? gl : gr, 0.f);
        if (gap * gap > dk7) break;
        int ns = left ? --sl : ++sr;
        process_slab(SP, CST, ns, gap, -1, -1, qx, qy, qz, dk_own, ik_own, dk7, lane);
    }

    if (lane < 8)
        g_idx[((size_t)b * N2 + q) * KNN + lane] = ik_own;
}

// ---------------------------------------------------------------------------
// Kernel 3: finalize, 4 sub-threads per query (16 channels each).
// h_n = lrelu(g[idx_n] - W1_xyz @ q);  w_j[n] = W2[j].h_n  (b2 cancels);
// softmax over n; dot with flow.
// ---------------------------------------------------------------------------
__device__ __forceinline__ float softmax_dot(const float (&w)[8],
                                             const float* __restrict__ f,
                                             const int (&ik)[8]) {
    float m = w[0];
#pragma unroll
    for (int n = 1; n < 8; n++) m = fmaxf(m, w[n]);
    float s = 0.f, acc = 0.f;
#pragma unroll
    for (int n = 0; n < 8; n++) {
        float e = __expf(w[n] - m);
        s += e;
        acc = fmaf(e, __ldg(f + ik[n]), acc);
    }
    return acc / s;
}

__global__ void __launch_bounds__(256) up_kernel(const float* __restrict__ xyz2,
                                                 const float* __restrict__ flow,
                                                 const float* __restrict__ W1,
                                                 const float* __restrict__ W2,
                                                 float* __restrict__ out) {
    __shared__ float sW2[3 * 64];   // [j][o]
    __shared__ float sWx[64 * 3];   // [o][c]  (xyz columns of W1)
    int t = threadIdx.x;
    if (t < 192) sW2[t] = W2[t];
    if (t < 192) { int o = t / 3, c = t - o * 3; sWx[t] = W1[o * 67 + 64 + c]; }
    __syncthreads();

    int qL = t >> 2;          // 0..63
    int s  = t & 3;
    int b  = blockIdx.x >> 8; // 256 blocks per batch
    int q  = ((blockIdx.x & 255) << 6) + qL;

    const float* xq = xyz2 + (size_t)b * 3 * N2;
    float qx = xq[q], qy = xq[N2 + q], qz = xq[2 * N2 + q];

    const int* ip = g_idx + ((size_t)b * N2 + q) * KNN;
    int ik[8];
    {
        int4 a  = ((const int4*)ip)[0];
        int4 c4 = ((const int4*)ip)[1];
        ik[0] = a.x;  ik[1] = a.y;  ik[2] = a.z;  ik[3] = a.w;
        ik[4] = c4.x; ik[5] = c4.y; ik[6] = c4.z; ik[7] = c4.w;
    }

    const float* gb = g_gtab + (size_t)b * N1 * CF;

    float a0[8], a1[8], a2[8];
#pragma unroll
    for (int n = 0; n < 8; n++) { a0[n] = 0.f; a1[n] = 0.f; a2[n] = 0.f; }

    // sub-thread s owns o4 blocks [4s, 4s+4) = channels [16s, 16s+16)
#pragma unroll
    for (int oo = 0; oo < 4; oo++) {
        int o4 = s * 4 + oo;
        int ob = o4 * 4;
        float uu[4], wa[4], wb[4], wc[4];
#pragma unroll
        for (int i = 0; i < 4; i++) {
            int o = ob + i;
            uu[i] = fmaf(sWx[o * 3 + 2], qz, fmaf(sWx[o * 3 + 1], qy, sWx[o * 3] * qx));
            wa[i] = sW2[o];
            wb[i] = sW2[64 + o];
            wc[i] = sW2[128 + o];
        }
#pragma unroll
        for (int n = 0; n < 8; n++) {
            float4 g4 = ((const float4*)(gb + (size_t)ik[n] * CF))[o4];
            float h;
            h = g4.x - uu[0]; h = h >= 0.f ? h : 0.1f * h;
            a0[n] = fmaf(wa[0], h, a0[n]); a1[n] = fmaf(wb[0], h, a1[n]); a2[n] = fmaf(wc[0], h, a2[n]);
            h = g4.y - uu[1]; h = h >= 0.f ? h : 0.1f * h;
            a0[n] = fmaf(wa[1], h, a0[n]); a1[n] = fmaf(wb[1], h, a1[n]); a2[n] = fmaf(wc[1], h, a2[n]);
            h = g4.z - uu[2]; h = h >= 0.f ? h : 0.1f * h;
            a0[n] = fmaf(wa[2], h, a0[n]); a1[n] = fmaf(wb[2], h, a1[n]); a2[n] = fmaf(wc[2], h, a2[n]);
            h = g4.w - uu[3]; h = h >= 0.f ? h : 0.1f * h;
            a0[n] = fmaf(wa[3], h, a0[n]); a1[n] = fmaf(wb[3], h, a1[n]); a2[n] = fmaf(wc[3], h, a2[n]);
        }
    }

    // reduce the 4 sub-threads' partials (lanes 4k..4k+3 hold one query)
    const unsigned FULL = 0xffffffffu;
#pragma unroll
    for (int d = 1; d <= 2; d <<= 1) {
#pragma unroll
        for (int n = 0; n < 8; n++) {
            a0[n] += __shfl_xor_sync(FULL, a0[n], d);
            a1[n] += __shfl_xor_sync(FULL, a1[n], d);
            a2[n] += __shfl_xor_sync(FULL, a2[n], d);
        }
    }

    if (s == 0) {
        const float* fb = flow + (size_t)b * 3 * N1;
        float* ob_ = out + (size_t)b * 3 * N2;
        ob_[q]          = softmax_dot(a0, fb, ik);
        ob_[N2 + q]     = softmax_dot(a1, fb + N1, ik);
        ob_[2 * N2 + q] = softmax_dot(a2, fb + 2 * N1, ik);
    }
}

// ---------------------------------------------------------------------------
extern "C" void kernel_launch(void* const* d_in, const int* in_sizes, int n_in,
                              void* d_out, int out_size) {
    const float* xyz1  = (const float*)d_in[0];
    const float* xyz2  = (const float*)d_in[1];
    const float* feat1 = (const float*)d_in[2];
    const float* flow  = (const float*)d_in[3];
    const float* W1    = (const float*)d_in[4];
    const float* b1    = (const float*)d_in[5];
    const float* W2    = (const float*)d_in[6];
    // b2 (d_in[7]) unused: constant shift cancels in softmax over k.
    float* out = (float*)d_out;

    prep_kernel<<<NB + NB * 64, 1024>>>(feat1, xyz1, W1, b1);
    knn_kernel<<<NB * 1024, 512>>>(xyz2);
    up_kernel<<<NB * 256, 256>>>(xyz2, flow, W1, W2, out);
}